// round 7
// baseline (speedup 1.0000x reference)
#include <cuda_runtime.h>
#include <cuda_bf16.h>
#include <mma.h>
#include <cstdint>

using namespace nvcuda;

// Problem constants
#define NB    4096
#define D_IN  512
#define D_FF  2048
#define D_OUT 512
#define NEXP  8
#define MAXTILES 48
#define ROWPAD 128

// ---------------------------------------------------------------------------
// Global scratch (no allocations allowed). All operands pre-truncated to tf32.
// ---------------------------------------------------------------------------
__device__ float g_xs[(NB + ROWPAD) * D_IN];        // sorted, tf32-rounded x
__device__ float g_w1[NEXP * D_IN * D_FF];          // tf32-rounded W1 [e][k][n]
__device__ float g_w2[NEXP * D_FF * D_OUT];         // tf32-rounded W2 [e][k][n]
__device__ float g_h[(NB + ROWPAD) * D_FF];         // sorted hidden, tf32-rounded
__device__ int   g_perm[NB];
__device__ int   g_segStart[NEXP + 1];
__device__ int   g_tileExpert[MAXTILES];
__device__ int   g_tileRow[MAXTILES];

// ---------------------------------------------------------------------------
// cp.async helpers
// ---------------------------------------------------------------------------
__device__ __forceinline__ void cp_async16(float* smem_dst, const float* gsrc) {
    unsigned int s = (unsigned int)__cvta_generic_to_shared(smem_dst);
    asm volatile("cp.async.cg.shared.global [%0], [%1], 16;\n" :: "r"(s), "l"(gsrc));
}
__device__ __forceinline__ void cp_commit() {
    asm volatile("cp.async.commit_group;\n");
}
template <int N>
__device__ __forceinline__ void cp_wait() {
    asm volatile("cp.async.wait_group %0;\n" :: "n"(N));
}

// ---------------------------------------------------------------------------
// Setup: histogram experts, prefix sum, scatter permutation, build tile map
// ---------------------------------------------------------------------------
__global__ void setup_kernel(const int* __restrict__ groups) {
    __shared__ int cnt[NEXP];
    __shared__ int base[NEXP];
    int tid = threadIdx.x;
    if (tid < NEXP) cnt[tid] = 0;
    __syncthreads();
    for (int b = tid; b < NB; b += blockDim.x)
        atomicAdd(&cnt[groups[2 * b]], 1);
    __syncthreads();
    if (tid == 0) {
        int s = 0;
        for (int e = 0; e < NEXP; e++) { g_segStart[e] = s; base[e] = s; s += cnt[e]; }
        g_segStart[NEXP] = s;
        int t = 0;
        for (int e = 0; e < NEXP; e++)
            for (int r = g_segStart[e]; r < g_segStart[e] + cnt[e]; r += 128) {
                g_tileExpert[t] = e; g_tileRow[t] = r; t++;
            }
        for (; t < MAXTILES; t++) g_tileExpert[t] = -1;
    }
    __syncthreads();
    for (int b = tid; b < NB; b += blockDim.x) {
        int e = groups[2 * b];
        int pos = atomicAdd(&base[e], 1);
        g_perm[pos] = b;   // segment-internal order nondeterministic; per-row results
                           // are permutation-invariant so output is deterministic.
    }
}

// ---------------------------------------------------------------------------
// x -> gathered (sorted) + tf32-rounded copy
// ---------------------------------------------------------------------------
__global__ void xcvt_kernel(const float* __restrict__ x) {
    int idx = blockIdx.x * 256 + threadIdx.x;     // NB * D_IN/4 threads
    int i  = idx >> 7;                            // row (sorted index)
    int kq = idx & 127;                           // float4 within row
    int src = g_perm[i];
    float4 v = *reinterpret_cast<const float4*>(x + (size_t)src * D_IN + kq * 4);
    v.x = wmma::__float_to_tf32(v.x);
    v.y = wmma::__float_to_tf32(v.y);
    v.z = wmma::__float_to_tf32(v.z);
    v.w = wmma::__float_to_tf32(v.w);
    *reinterpret_cast<float4*>(g_xs + (size_t)i * D_IN + kq * 4) = v;
}

// ---------------------------------------------------------------------------
// W -> tf32-rounded copy (same layout)
// ---------------------------------------------------------------------------
__global__ void wcvt_kernel(const float* __restrict__ W, float* __restrict__ Wo,
                            int n4) {
    int idx = blockIdx.x * 256 + threadIdx.x;
    if (idx < n4) {
        float4 v = *reinterpret_cast<const float4*>(W + (size_t)idx * 4);
        v.x = wmma::__float_to_tf32(v.x);
        v.y = wmma::__float_to_tf32(v.y);
        v.z = wmma::__float_to_tf32(v.z);
        v.w = wmma::__float_to_tf32(v.w);
        *reinterpret_cast<float4*>(Wo + (size_t)idx * 4) = v;
    }
}

// ---------------------------------------------------------------------------
// Grouped GEMM, TF32 wmma, 2-stage cp.async pipeline, pre-rounded operands
// (no per-fragment conversions). BM=128, BK=32, BN templated.
// 8 warps: 2 in M x 4 in N.
// PASS1: A = g_xs (sorted), out = tf32(relu(acc+b1)) -> g_h (sorted)
// PASS2: A = g_h (sorted),  out[perm[i]] = acc+b2 -> Y
// ---------------------------------------------------------------------------
#define BM  128
#define BK  32
#define LDA (BK + 4)    // stride mod 32 == 4 -> 8-row conflict-free groups

template <int BN, int K, int NFULL, bool PASS1>
__launch_bounds__(256)
__global__ void gemm_kernel(const float* __restrict__ A,
                            const float* __restrict__ W,
                            const float* __restrict__ bias,
                            float* __restrict__ Y) {
    constexpr int LDB = BN + 4;
    constexpr int WN  = BN / 4;     // warp tile N
    constexpr int NF  = WN / 16;    // n-fragments per warp
    constexpr int NQ  = BN / 4;     // float4 per B row
    constexpr int STAGE = BM * LDA + BK * LDB;

    extern __shared__ __align__(128) float dynSmem[];
    __shared__ __align__(32) float sEpi[8][256];
    __shared__ int sDst[BM];

    int e = g_tileExpert[blockIdx.x];
    if (e < 0) return;
    int rowStart = g_tileRow[blockIdx.x];
    int segEnd   = g_segStart[e + 1];
    int n0 = blockIdx.y * BN;

    int tid = threadIdx.x;
    if (tid < BM) {
        int i = rowStart + tid;
        if (PASS1) sDst[tid] = (i < segEnd) ? i : -1;
        else       sDst[tid] = (i < segEnd) ? g_perm[i] : -1;
    }
    __syncthreads();

    const float* Wb = W + (size_t)e * K * NFULL;

    int warpId = tid >> 5;
    int warpM  = warpId & 1;
    int warpN  = warpId >> 1;
    int lane   = tid & 31;

    wmma::fragment<wmma::accumulator, 16, 16, 8, float> acc[4][NF];
#pragma unroll
    for (int mi = 0; mi < 4; mi++)
#pragma unroll
        for (int ni = 0; ni < NF; ni++) wmma::fill_fragment(acc[mi][ni], 0.0f);

    constexpr int NT = K / BK;

    auto loadStage = [&](int s, int k0) {
        float* sA = dynSmem + s * STAGE;
        float* sB = sA + BM * LDA;
#pragma unroll
        for (int f = tid; f < BM * BK / 4; f += 256) {      // 1024 units
            int r  = f >> 3;
            int kq = f & 7;
            cp_async16(&sA[r * LDA + kq * 4],
                       A + (size_t)(rowStart + r) * K + k0 + kq * 4);
        }
#pragma unroll
        for (int f = tid; f < BK * NQ; f += 256) {
            int kr = f / NQ;
            int nq = f % NQ;
            cp_async16(&sB[kr * LDB + nq * 4],
                       Wb + (size_t)(k0 + kr) * NFULL + n0 + nq * 4);
        }
    };

    loadStage(0, 0);
    cp_commit();

    for (int t = 0; t < NT; t++) {
        if (t + 1 < NT) loadStage((t + 1) & 1, (t + 1) * BK);
        cp_commit();
        cp_wait<1>();
        __syncthreads();

        const float* sA = dynSmem + (t & 1) * STAGE;
        const float* sB = sA + BM * LDA;

#pragma unroll
        for (int kk = 0; kk < BK; kk += 8) {
            wmma::fragment<wmma::matrix_a, 16, 16, 8, wmma::precision::tf32,
                           wmma::row_major> af[4];
            wmma::fragment<wmma::matrix_b, 16, 16, 8, wmma::precision::tf32,
                           wmma::row_major> bf[NF];
#pragma unroll
            for (int mi = 0; mi < 4; mi++)
                wmma::load_matrix_sync(af[mi],
                    &sA[(warpM * 64 + mi * 16) * LDA + kk], LDA);
#pragma unroll
            for (int ni = 0; ni < NF; ni++)
                wmma::load_matrix_sync(bf[ni],
                    &sB[kk * LDB + warpN * WN + ni * 16], LDB);
            // operands pre-rounded to tf32 in global memory: no cvt loops
#pragma unroll
            for (int mi = 0; mi < 4; mi++)
#pragma unroll
                for (int ni = 0; ni < NF; ni++)
                    wmma::mma_sync(acc[mi][ni], af[mi], bf[ni], acc[mi][ni]);
        }
        __syncthreads();
    }

    // Epilogue: bounce fragments through smem, bias (+relu +tf32-round pass1),
    // mask invalid rows, scatter (pass2).
#pragma unroll
    for (int mi = 0; mi < 4; mi++) {
#pragma unroll
        for (int ni = 0; ni < NF; ni++) {
            wmma::store_matrix_sync(&sEpi[warpId][0], acc[mi][ni], 16,
                                    wmma::mem_row_major);
            __syncwarp();
#pragma unroll
            for (int q = 0; q < 8; q++) {
                int idx = lane + q * 32;
                int r = idx >> 4, c = idx & 15;
                int lr  = warpM * 64 + mi * 16 + r;
                int dst = sDst[lr];
                if (dst >= 0) {
                    int n = n0 + warpN * WN + ni * 16 + c;
                    float v = sEpi[warpId][idx] + bias[e * NFULL + n];
                    if (PASS1) {
                        v = wmma::__float_to_tf32(fmaxf(v, 0.0f));
                        g_h[(size_t)dst * NFULL + n] = v;
                    } else {
                        Y[(size_t)dst * NFULL + n] = v;
                    }
                }
            }
            __syncwarp();
        }
    }
}

// ---------------------------------------------------------------------------
extern "C" void kernel_launch(void* const* d_in, const int* in_sizes, int n_in,
                              void* d_out, int out_size) {
    const float* x      = (const float*)d_in[0];
    const int*   groups = (const int*)d_in[1];
    const float* W1     = (const float*)d_in[2];
    const float* b1     = (const float*)d_in[3];
    const float* W2     = (const float*)d_in[4];
    const float* b2     = (const float*)d_in[5];
    float* out = (float*)d_out;

    constexpr int SMEM1 = 2 * (BM * (BK + 4) + BK * (128 + 4)) * 4;  // 70656 B
    constexpr int SMEM2 = 2 * (BM * (BK + 4) + BK * (64 + 4)) * 4;   // 54272 B

    static bool attrDone = false;
    if (!attrDone) {
        cudaFuncSetAttribute(gemm_kernel<128, D_IN, D_FF, true>,
                             cudaFuncAttributeMaxDynamicSharedMemorySize, SMEM1);
        cudaFuncSetAttribute(gemm_kernel<64, D_FF, D_OUT, false>,
                             cudaFuncAttributeMaxDynamicSharedMemorySize, SMEM2);
        attrDone = true;
    }

    float *xs, *w1, *w2, *h;
    cudaGetSymbolAddress((void**)&xs, g_xs);
    cudaGetSymbolAddress((void**)&w1, g_w1);
    cudaGetSymbolAddress((void**)&w2, g_w2);
    cudaGetSymbolAddress((void**)&h,  g_h);

    setup_kernel<<<1, 512>>>(groups);
    xcvt_kernel<<<(NB * (D_IN / 4)) / 256, 256>>>(x);
    {
        int n4 = NEXP * D_IN * D_FF / 4;
        wcvt_kernel<<<(n4 + 255) / 256, 256>>>(W1, w1, n4);
    }
    {
        int n4 = NEXP * D_FF * D_OUT / 4;
        wcvt_kernel<<<(n4 + 255) / 256, 256>>>(W2, w2, n4);
    }

    // Pass 1: h = tf32(relu(x_sorted @ W1[e] + b1[e])) -> g_h (sorted)
    gemm_kernel<128, D_IN, D_FF, true>
        <<<dim3(MAXTILES, D_FF / 128), 256, SMEM1>>>(xs, w1, b1, nullptr);

    // Pass 2: out[perm] = g_h @ W2[e] + b2[e]
    gemm_kernel<64, D_FF, D_OUT, false>
        <<<dim3(MAXTILES, D_OUT / 64), 256, SMEM2>>>(h, w2, b2, out);
}

// round 9
// speedup vs baseline: 3.3359x; 3.3359x over previous
#include <cuda_runtime.h>
#include <cuda_fp16.h>
#include <mma.h>
#include <cstdint>

using namespace nvcuda;

// Problem constants
#define NB    4096
#define D_IN  512
#define D_FF  2048
#define D_OUT 512
#define NEXP  8
#define MAXTILES 48
#define ROWPAD 128

// ---------------------------------------------------------------------------
// Global scratch (no allocations allowed). Operands converted to fp16
// (10-bit mantissa == tf32 precision), fp32 accumulate.
// ---------------------------------------------------------------------------
__device__ __half g_xs[(NB + ROWPAD) * D_IN];   // sorted fp16 x
__device__ __half g_w1[NEXP * D_IN * D_FF];     // fp16 W1 [e][k][n]
__device__ __half g_w2[NEXP * D_FF * D_OUT];    // fp16 W2 [e][k][n]
__device__ __half g_h[(NB + ROWPAD) * D_FF];    // sorted fp16 hidden
__device__ int    g_perm[NB];
__device__ int    g_segStart[NEXP + 1];
__device__ int    g_tileExpert[MAXTILES];
__device__ int    g_tileRow[MAXTILES];

// ---------------------------------------------------------------------------
// cp.async helpers (16B = 8 halves)
// ---------------------------------------------------------------------------
__device__ __forceinline__ void cp_async16(__half* smem_dst, const __half* gsrc) {
    unsigned int s = (unsigned int)__cvta_generic_to_shared(smem_dst);
    asm volatile("cp.async.cg.shared.global [%0], [%1], 16;\n" :: "r"(s), "l"(gsrc));
}
__device__ __forceinline__ void cp_commit() {
    asm volatile("cp.async.commit_group;\n");
}
template <int N>
__device__ __forceinline__ void cp_wait() {
    asm volatile("cp.async.wait_group %0;\n" :: "n"(N));
}

// ---------------------------------------------------------------------------
// Setup: histogram experts, prefix sum, scatter permutation, build tile map
// ---------------------------------------------------------------------------
__global__ void setup_kernel(const int* __restrict__ groups) {
    __shared__ int cnt[NEXP];
    __shared__ int base[NEXP];
    int tid = threadIdx.x;
    if (tid < NEXP) cnt[tid] = 0;
    __syncthreads();
    for (int b = tid; b < NB; b += blockDim.x)
        atomicAdd(&cnt[groups[2 * b]], 1);
    __syncthreads();
    if (tid == 0) {
        int s = 0;
        for (int e = 0; e < NEXP; e++) { g_segStart[e] = s; base[e] = s; s += cnt[e]; }
        g_segStart[NEXP] = s;
        int t = 0;
        for (int e = 0; e < NEXP; e++)
            for (int r = g_segStart[e]; r < g_segStart[e] + cnt[e]; r += 128) {
                g_tileExpert[t] = e; g_tileRow[t] = r; t++;
            }
        for (; t < MAXTILES; t++) g_tileExpert[t] = -1;
    }
    __syncthreads();
    for (int b = tid; b < NB; b += blockDim.x) {
        int e = groups[2 * b];
        int pos = atomicAdd(&base[e], 1);
        g_perm[pos] = b;   // segment-internal order nondeterministic; per-row results
                           // are permutation-invariant so output is deterministic.
    }
}

// ---------------------------------------------------------------------------
// x -> gathered (sorted) fp16. 8 floats per thread -> 8 halves (16B store).
// ---------------------------------------------------------------------------
__global__ void xcvt_kernel(const float* __restrict__ x) {
    int idx = blockIdx.x * 256 + threadIdx.x;   // NB * D_IN/8 threads
    int i = idx >> 6;                           // sorted row
    int q = idx & 63;                           // 8-float chunk
    int src = g_perm[i];
    const float4* s = reinterpret_cast<const float4*>(x + (size_t)src * D_IN + q * 8);
    float4 a = s[0], b = s[1];
    __half2 h0 = __floats2half2_rn(a.x, a.y);
    __half2 h1 = __floats2half2_rn(a.z, a.w);
    __half2 h2 = __floats2half2_rn(b.x, b.y);
    __half2 h3 = __floats2half2_rn(b.z, b.w);
    uint4 o = make_uint4(*(unsigned*)&h0, *(unsigned*)&h1, *(unsigned*)&h2, *(unsigned*)&h3);
    *reinterpret_cast<uint4*>(g_xs + (size_t)i * D_IN + q * 8) = o;
}

// ---------------------------------------------------------------------------
// W fp32 -> fp16 (same layout). 8 floats per thread.
// ---------------------------------------------------------------------------
__global__ void wcvt_kernel(const float* __restrict__ W, __half* __restrict__ Wo,
                            int n8) {
    int idx = blockIdx.x * 256 + threadIdx.x;
    if (idx < n8) {
        const float4* s = reinterpret_cast<const float4*>(W + (size_t)idx * 8);
        float4 a = s[0], b = s[1];
        __half2 h0 = __floats2half2_rn(a.x, a.y);
        __half2 h1 = __floats2half2_rn(a.z, a.w);
        __half2 h2 = __floats2half2_rn(b.x, b.y);
        __half2 h3 = __floats2half2_rn(b.z, b.w);
        uint4 o = make_uint4(*(unsigned*)&h0, *(unsigned*)&h1, *(unsigned*)&h2, *(unsigned*)&h3);
        *reinterpret_cast<uint4*>(Wo + (size_t)idx * 8) = o;
    }
}

// ---------------------------------------------------------------------------
// Grouped GEMM, fp16 wmma m16n16k16, fp32 accumulate.
// BM=128, BN=128, BK=64 halves. 2-stage cp.async pipeline.
// 8 warps: 2 in M x 4 in N, warp tile 64x32.
// PASS1: A = g_xs (sorted), out = fp16(relu(acc+b1)) -> g_h (sorted)
// PASS2: A = g_h (sorted),  out[perm[i]] = acc+b2 -> Y (fp32)
// ---------------------------------------------------------------------------
#define BM  128
#define BN  128
#define BK  64
#define LDA (BK + 8)   // 72 halves = 144B row stride
#define LDB (BN + 8)   // 136 halves = 272B row stride
#define STAGE_HALVES (BM * LDA + BK * LDB)      // 17920
#define SMEM_DYN (2 * STAGE_HALVES * 2)          // 71680 B

template <int K, int NFULL, bool PASS1>
__launch_bounds__(256)
__global__ void gemm_kernel(const __half* __restrict__ A,
                            const __half* __restrict__ W,
                            const float* __restrict__ bias,
                            float* __restrict__ Y) {
    constexpr int WN = BN / 4;    // 32
    constexpr int NF = WN / 16;   // 2

    extern __shared__ __align__(128) __half dynSmem[];
    __shared__ __align__(32) float sEpi[8][256];
    __shared__ int sDst[BM];

    int e = g_tileExpert[blockIdx.x];
    if (e < 0) return;
    int rowStart = g_tileRow[blockIdx.x];
    int segEnd   = g_segStart[e + 1];
    int n0 = blockIdx.y * BN;

    int tid = threadIdx.x;
    if (tid < BM) {
        int i = rowStart + tid;
        if (PASS1) sDst[tid] = (i < segEnd) ? i : -1;
        else       sDst[tid] = (i < segEnd) ? g_perm[i] : -1;
    }
    __syncthreads();

    const __half* Wb = W + (size_t)e * K * NFULL;

    int warpId = tid >> 5;
    int warpM  = warpId & 1;
    int warpN  = warpId >> 1;
    int lane   = tid & 31;

    wmma::fragment<wmma::accumulator, 16, 16, 16, float> acc[4][NF];
#pragma unroll
    for (int mi = 0; mi < 4; mi++)
#pragma unroll
        for (int ni = 0; ni < NF; ni++) wmma::fill_fragment(acc[mi][ni], 0.0f);

    constexpr int NT = K / BK;

    auto loadStage = [&](int s, int k0) {
        __half* sA = dynSmem + s * STAGE_HALVES;
        __half* sB = sA + BM * LDA;
#pragma unroll
        for (int f = tid; f < BM * (BK / 8); f += 256) {     // 1024 units
            int r = f >> 3, q = f & 7;
            cp_async16(&sA[r * LDA + q * 8],
                       A + (size_t)(rowStart + r) * K + k0 + q * 8);
        }
#pragma unroll
        for (int f = tid; f < BK * (BN / 8); f += 256) {     // 1024 units
            int kr = f >> 4, nq = f & 15;
            cp_async16(&sB[kr * LDB + nq * 8],
                       Wb + (size_t)(k0 + kr) * NFULL + n0 + nq * 8);
        }
    };

    loadStage(0, 0);
    cp_commit();

    for (int t = 0; t < NT; t++) {
        if (t + 1 < NT) loadStage((t + 1) & 1, (t + 1) * BK);
        cp_commit();
        cp_wait<1>();
        __syncthreads();

        const __half* sA = dynSmem + (t & 1) * STAGE_HALVES;
        const __half* sB = sA + BM * LDA;

#pragma unroll
        for (int kk = 0; kk < BK; kk += 16) {
            wmma::fragment<wmma::matrix_a, 16, 16, 16, __half, wmma::row_major> af[4];
            wmma::fragment<wmma::matrix_b, 16, 16, 16, __half, wmma::row_major> bf[NF];
#pragma unroll
            for (int mi = 0; mi < 4; mi++)
                wmma::load_matrix_sync(af[mi],
                    &sA[(warpM * 64 + mi * 16) * LDA + kk], LDA);
#pragma unroll
            for (int ni = 0; ni < NF; ni++)
                wmma::load_matrix_sync(bf[ni],
                    &sB[kk * LDB + warpN * WN + ni * 16], LDB);
#pragma unroll
            for (int mi = 0; mi < 4; mi++)
#pragma unroll
                for (int ni = 0; ni < NF; ni++)
                    wmma::mma_sync(acc[mi][ni], af[mi], bf[ni], acc[mi][ni]);
        }
        __syncthreads();
    }

    // Epilogue: bounce fragments through smem, bias (+relu, fp16 for pass1),
    // mask invalid rows, scatter (pass2).
#pragma unroll
    for (int mi = 0; mi < 4; mi++) {
#pragma unroll
        for (int ni = 0; ni < NF; ni++) {
            wmma::store_matrix_sync(&sEpi[warpId][0], acc[mi][ni], 16,
                                    wmma::mem_row_major);
            __syncwarp();
#pragma unroll
            for (int q = 0; q < 8; q++) {
                int idx = lane + q * 32;
                int r = idx >> 4, c = idx & 15;
                int lr  = warpM * 64 + mi * 16 + r;
                int dst = sDst[lr];
                if (dst >= 0) {
                    int n = n0 + warpN * WN + ni * 16 + c;
                    float v = sEpi[warpId][idx] + bias[e * NFULL + n];
                    if (PASS1) {
                        g_h[(size_t)dst * NFULL + n] = __float2half(fmaxf(v, 0.0f));
                    } else {
                        Y[(size_t)dst * NFULL + n] = v;
                    }
                }
            }
            __syncwarp();
        }
    }
}

// ---------------------------------------------------------------------------
extern "C" void kernel_launch(void* const* d_in, const int* in_sizes, int n_in,
                              void* d_out, int out_size) {
    const float* x      = (const float*)d_in[0];
    const int*   groups = (const int*)d_in[1];
    const float* W1     = (const float*)d_in[2];
    const float* b1     = (const float*)d_in[3];
    const float* W2     = (const float*)d_in[4];
    const float* b2     = (const float*)d_in[5];
    float* out = (float*)d_out;

    static bool attrDone = false;
    if (!attrDone) {
        cudaFuncSetAttribute(gemm_kernel<D_IN, D_FF, true>,
                             cudaFuncAttributeMaxDynamicSharedMemorySize, SMEM_DYN);
        cudaFuncSetAttribute(gemm_kernel<D_FF, D_OUT, false>,
                             cudaFuncAttributeMaxDynamicSharedMemorySize, SMEM_DYN);
        attrDone = true;
    }

    __half *xs, *w1, *w2, *h;
    cudaGetSymbolAddress((void**)&xs, g_xs);
    cudaGetSymbolAddress((void**)&w1, g_w1);
    cudaGetSymbolAddress((void**)&w2, g_w2);
    cudaGetSymbolAddress((void**)&h,  g_h);

    setup_kernel<<<1, 512>>>(groups);
    xcvt_kernel<<<(NB * (D_IN / 8)) / 256, 256>>>(x);
    {
        int n8 = NEXP * D_IN * D_FF / 8;
        wcvt_kernel<<<(n8 + 255) / 256, 256>>>(W1, w1, n8);
    }
    {
        int n8 = NEXP * D_FF * D_OUT / 8;
        wcvt_kernel<<<(n8 + 255) / 256, 256>>>(W2, w2, n8);
    }

    // Pass 1: h = fp16(relu(x_sorted @ W1[e] + b1[e])) -> g_h (sorted)
    gemm_kernel<D_IN, D_FF, true>
        <<<dim3(MAXTILES, D_FF / BN), 256, SMEM_DYN>>>(xs, w1, b1, nullptr);

    // Pass 2: out[perm] = g_h @ W2[e] + b2[e]
    gemm_kernel<D_FF, D_OUT, false>
        <<<dim3(MAXTILES, D_OUT / BN), 256, SMEM_DYN>>>(h, w2, b2, out);
}